// round 2
// baseline (speedup 1.0000x reference)
#include <cuda_runtime.h>

#define NN 50000
#define EE 800000
#define D  128

// ---------------- persistent device scratch --------------------------------
__device__ int   g_degE[NN];
__device__ float g_dinv[NN];
__device__ int   g_rowPtr[NN + 1];
__device__ int   g_cursor[NN];
__device__ int   g_blkSum[64];
__device__ int   g_src[EE];
__device__ float g_h[(size_t)NN * D];
__device__ float g_a[(size_t)NN * D];
__device__ float g_gsum[D];

// ---------------- setup -----------------------------------------------------
__global__ void k_init() {
    int i = blockIdx.x * blockDim.x + threadIdx.x;
    if (i < NN) { g_degE[i] = 0; g_cursor[i] = 0; }
    if (i < D) g_gsum[i] = 0.f;
    if (i == 0) g_rowPtr[NN] = EE;
}

__global__ void k_count4(const int4* __restrict__ col4) {
    int idx = blockIdx.x * blockDim.x + threadIdx.x;
    if (idx < EE / 4) {
        int4 c = __ldg(&col4[idx]);
        atomicAdd(&g_degE[c.x], 1);
        atomicAdd(&g_degE[c.y], 1);
        atomicAdd(&g_degE[c.z], 1);
        atomicAdd(&g_degE[c.w], 1);
    }
}

// block-level scan (49 blocks x 1024)
__global__ void k_scanA() {
    __shared__ int sW[32];
    int t = threadIdx.x, b = blockIdx.x;
    int i = b * 1024 + t;
    int v = (i < NN) ? g_degE[i] : 0;
    if (i < NN) g_dinv[i] = rsqrtf((float)(v + 1));   // +1 self loop
    int lane = t & 31, wid = t >> 5;
    int incl = v;
#pragma unroll
    for (int d = 1; d < 32; d <<= 1) {
        int n = __shfl_up_sync(0xffffffffu, incl, d);
        if (lane >= d) incl += n;
    }
    if (lane == 31) sW[wid] = incl;
    __syncthreads();
    if (wid == 0) {
        int wv = sW[lane];
#pragma unroll
        for (int d = 1; d < 32; d <<= 1) {
            int n = __shfl_up_sync(0xffffffffu, wv, d);
            if (lane >= d) wv += n;
        }
        sW[lane] = wv;
    }
    __syncthreads();
    int woff = (wid > 0) ? sW[wid - 1] : 0;
    if (i < NN) g_rowPtr[i] = woff + incl - v;   // block-local exclusive
    if (t == 1023) g_blkSum[b] = woff + incl;    // block total
}

__global__ void k_scanB() {
    __shared__ int sArr[64];
    __shared__ int sOff;
    int t = threadIdx.x, b = blockIdx.x;
    if (t < 49) sArr[t] = g_blkSum[t];
    __syncthreads();
    if (t == 0) { int s = 0; for (int j = 0; j < b; j++) s += sArr[j]; sOff = s; }
    __syncthreads();
    int i = b * 1024 + t;
    if (i < NN) g_rowPtr[i] += sOff;
}

__global__ void k_scatter4(const int4* __restrict__ row4, const int4* __restrict__ col4) {
    int idx = blockIdx.x * blockDim.x + threadIdx.x;
    if (idx < EE / 4) {
        int4 r = __ldg(&row4[idx]);
        int4 c = __ldg(&col4[idx]);
        g_src[__ldg(&g_rowPtr[c.x]) + atomicAdd(&g_cursor[c.x], 1)] = r.x;
        g_src[__ldg(&g_rowPtr[c.y]) + atomicAdd(&g_cursor[c.y], 1)] = r.y;
        g_src[__ldg(&g_rowPtr[c.z]) + atomicAdd(&g_cursor[c.z], 1)] = r.z;
        g_src[__ldg(&g_rowPtr[c.w]) + atomicAdd(&g_cursor[c.w], 1)] = r.w;
    }
}

// ---------------- tensor-core GEMM (3xTF32): Y = X @ W ----------------------
// Block: 256 thr (8 warps), tile M=128, N=128, K chunked by 16.
// Smem stores hi/lo tf32 splits PRE-SHUFFLED into mma fragment order so each
// A/B fragment group is one LDS.128.
__device__ __forceinline__ void split_tf32(float x, unsigned& hi, unsigned& lo) {
    asm("cvt.rna.tf32.f32 %0, %1;" : "=r"(hi) : "f"(x));
    float r = x - __uint_as_float(hi);
    asm("cvt.rna.tf32.f32 %0, %1;" : "=r"(lo) : "f"(r));
}

__device__ __forceinline__ void mma_tf32(float* d, const unsigned* a, unsigned b0, unsigned b1) {
    asm volatile(
        "mma.sync.aligned.m16n8k8.row.col.f32.tf32.tf32.f32 "
        "{%0,%1,%2,%3},{%4,%5,%6,%7},{%8,%9},{%0,%1,%2,%3};\n"
        : "+f"(d[0]), "+f"(d[1]), "+f"(d[2]), "+f"(d[3])
        : "r"(a[0]), "r"(a[1]), "r"(a[2]), "r"(a[3]), "r"(b0), "r"(b1));
}

__global__ void __launch_bounds__(256) k_gemm_tc(const float* __restrict__ X,
                                                 const float* __restrict__ W,
                                                 float* __restrict__ Y) {
    // sA: [hi 2048][lo 2048] floats; group (mt,ks,lane) -> 4 consecutive floats
    // sB: 4096 floats; group (nt,ks,lane) -> [b0h,b1h,b0l,b1l]
    __shared__ float sA[4096];
    __shared__ float sB[4096];

    const int t = threadIdx.x;
    const int lane = t & 31;
    const int w = t >> 5;
    const int wm = w >> 2;          // 0..1  (m direction, 64 rows each)
    const int wn = w & 3;           // 0..3  (n direction, 32 cols each)
    const int blkRow = blockIdx.x * 128;

    float acc[4][4][4];
#pragma unroll
    for (int i = 0; i < 4; i++)
#pragma unroll
        for (int j = 0; j < 4; j++)
#pragma unroll
            for (int k = 0; k < 4; k++) acc[i][j][k] = 0.f;

    for (int c = 0; c < 8; c++) {
        const int k0 = c * 16;
        // ---- stage A (X[blkRow:blkRow+128, k0:k0+16]) ----
#pragma unroll
        for (int pass = 0; pass < 2; pass++) {
            int rloc = (t >> 2) + pass * 64;          // 0..127
            int kloc4 = (t & 3) * 4;                  // 0,4,8,12
            int r = blkRow + rloc;
            float4 xv = (r < NN) ? *(const float4*)(X + (size_t)r * 128 + k0 + kloc4)
                                 : make_float4(0.f, 0.f, 0.f, 0.f);
            const float xs[4] = {xv.x, xv.y, xv.z, xv.w};
#pragma unroll
            for (int j = 0; j < 4; j++) {
                int kk = kloc4 + j;
                int mt = rloc >> 4, rr = rloc & 15;
                int ks = kk >> 3, k8 = kk & 7;
                int ln = (rr & 7) * 4 + (k8 & 3);
                int reg = (rr >> 3) + ((k8 >> 2) << 1);
                int idx = ((mt * 2 + ks) * 32 + ln) * 4 + reg;
                unsigned hi, lo;
                split_tf32(xs[j], hi, lo);
                sA[idx] = __uint_as_float(hi);
                sA[2048 + idx] = __uint_as_float(lo);
            }
        }
        // ---- stage B (W[k0:k0+16, 0:128]) ----
        {
            int kk = t >> 4;                 // 0..15
            int n0 = (t & 15) * 8;           // 0..120
            const float* wrow = W + (size_t)(k0 + kk) * 128 + n0;
            float4 w0 = *(const float4*)(wrow);
            float4 w1 = *(const float4*)(wrow + 4);
            const float wv[8] = {w0.x, w0.y, w0.z, w0.w, w1.x, w1.y, w1.z, w1.w};
            int ks = kk >> 3, k8 = kk & 7;
            int pos = (k8 >> 2);             // 0 or 1 (b0/b1)
#pragma unroll
            for (int j = 0; j < 8; j++) {
                int n = n0 + j;
                int nt = n >> 3, nn = n & 7;
                int ln = nn * 4 + (k8 & 3);
                int base = ((nt * 2 + ks) * 32 + ln) * 4;
                unsigned hi, lo;
                split_tf32(wv[j], hi, lo);
                sB[base + pos] = __uint_as_float(hi);
                sB[base + 2 + pos] = __uint_as_float(lo);
            }
        }
        __syncthreads();

        // ---- compute ----
#pragma unroll
        for (int ks = 0; ks < 2; ks++) {
            uint4 bb[4];
#pragma unroll
            for (int nt = 0; nt < 4; nt++) {
                int ntg = wn * 4 + nt;
                bb[nt] = *(const uint4*)(sB + ((ntg * 2 + ks) * 32 + lane) * 4);
            }
#pragma unroll
            for (int mt = 0; mt < 4; mt++) {
                int mtg = wm * 4 + mt;
                int base = ((mtg * 2 + ks) * 32 + lane) * 4;
                uint4 ah4 = *(const uint4*)(sA + base);
                uint4 al4 = *(const uint4*)(sA + 2048 + base);
                unsigned ah[4] = {ah4.x, ah4.y, ah4.z, ah4.w};
                unsigned al[4] = {al4.x, al4.y, al4.z, al4.w};
#pragma unroll
                for (int nt = 0; nt < 4; nt++) {
                    mma_tf32(acc[mt][nt], al, bb[nt].x, bb[nt].y);   // Al*Bh
                    mma_tf32(acc[mt][nt], ah, bb[nt].z, bb[nt].w);   // Ah*Bl
                    mma_tf32(acc[mt][nt], ah, bb[nt].x, bb[nt].y);   // Ah*Bh
                }
            }
        }
        __syncthreads();
    }

    // ---- epilogue ----
#pragma unroll
    for (int mt = 0; mt < 4; mt++) {
#pragma unroll
        for (int nt = 0; nt < 4; nt++) {
            int row = blkRow + wm * 64 + mt * 16 + (lane >> 2);
            int col = wn * 32 + nt * 8 + (lane & 3) * 2;
            if (row < NN)
                *(float2*)(Y + (size_t)row * 128 + col) =
                    make_float2(acc[mt][nt][0], acc[mt][nt][1]);
            if (row + 8 < NN)
                *(float2*)(Y + (size_t)(row + 8) * 128 + col) =
                    make_float2(acc[mt][nt][2], acc[mt][nt][3]);
        }
    }
}

// ---------------- sparse aggregation (warp per node) -----------------------
template <bool POOL>
__global__ void __launch_bounds__(256) k_agg(const float* __restrict__ H,
                                             const float* __restrict__ bias,
                                             float* __restrict__ O) {
    __shared__ float sPool[128];
    const int lane = threadIdx.x & 31;
    const int w = threadIdx.x >> 5;
    if (POOL) {
        if (threadIdx.x < 128) sPool[threadIdx.x] = 0.f;
        __syncthreads();
    }
    const int node = blockIdx.x * 8 + w;
    if (node < NN) {
        const int s = g_rowPtr[node];
        const int e = g_rowPtr[node + 1];
        const float4* Hv = (const float4*)H;
        float4 acc0 = make_float4(0.f, 0.f, 0.f, 0.f);
        float4 acc1 = make_float4(0.f, 0.f, 0.f, 0.f);
        int i = s;
        for (; i + 1 < e; i += 2) {
            int r0 = __ldg(&g_src[i]);
            int r1 = __ldg(&g_src[i + 1]);
            float d0 = g_dinv[r0], d1 = g_dinv[r1];
            float4 v0 = Hv[(size_t)r0 * 32 + lane];
            float4 v1 = Hv[(size_t)r1 * 32 + lane];
            acc0.x += d0 * v0.x; acc0.y += d0 * v0.y;
            acc0.z += d0 * v0.z; acc0.w += d0 * v0.w;
            acc1.x += d1 * v1.x; acc1.y += d1 * v1.y;
            acc1.z += d1 * v1.z; acc1.w += d1 * v1.w;
        }
        if (i < e) {
            int r0 = __ldg(&g_src[i]);
            float d0 = g_dinv[r0];
            float4 v0 = Hv[(size_t)r0 * 32 + lane];
            acc0.x += d0 * v0.x; acc0.y += d0 * v0.y;
            acc0.z += d0 * v0.z; acc0.w += d0 * v0.w;
        }
        acc0.x += acc1.x; acc0.y += acc1.y; acc0.z += acc1.z; acc0.w += acc1.w;
        const float dc = g_dinv[node];
        const float dc2 = dc * dc;
        float4 sv = Hv[(size_t)node * 32 + lane];
        float4 b = ((const float4*)bias)[lane];
        float4 res;
        res.x = fmaxf(dc * acc0.x + dc2 * sv.x + b.x, 0.f);
        res.y = fmaxf(dc * acc0.y + dc2 * sv.y + b.y, 0.f);
        res.z = fmaxf(dc * acc0.z + dc2 * sv.z + b.z, 0.f);
        res.w = fmaxf(dc * acc0.w + dc2 * sv.w + b.w, 0.f);
        if (!POOL) {
            *(float4*)(O + (size_t)node * 128 + lane * 4) = res;
        } else {
            atomicAdd(&sPool[lane * 4 + 0], res.x);
            atomicAdd(&sPool[lane * 4 + 1], res.y);
            atomicAdd(&sPool[lane * 4 + 2], res.z);
            atomicAdd(&sPool[lane * 4 + 3], res.w);
        }
    }
    if (POOL) {
        __syncthreads();
        if (threadIdx.x < 128) atomicAdd(&g_gsum[threadIdx.x], sPool[threadIdx.x]);
    }
}

// ---------------- classifier head -------------------------------------------
__global__ void k_cls(const float* __restrict__ Wc, const float* __restrict__ bc,
                      float* __restrict__ out) {
    int o = threadIdx.x;
    if (o < 40) {
        float acc = 0.f;
        for (int k = 0; k < 128; k++) acc += g_gsum[k] * Wc[k * 40 + o];
        out[o] = acc * (1.0f / (float)NN) + bc[o];
    }
}

// ---------------- launch -----------------------------------------------------
extern "C" void kernel_launch(void* const* d_in, const int* in_sizes, int n_in,
                              void* d_out, int out_size) {
    const float* x  = (const float*)d_in[0];
    const int*   ei = (const int*)d_in[1];
    const float* W1 = (const float*)d_in[2];
    const float* b1 = (const float*)d_in[3];
    const float* W2 = (const float*)d_in[4];
    const float* b2 = (const float*)d_in[5];
    const float* Wc = (const float*)d_in[6];
    const float* bc = (const float*)d_in[7];
    const int* row = ei;
    const int* col = ei + EE;

    float *h_ptr, *a_ptr;
    cudaGetSymbolAddress((void**)&h_ptr, g_h);
    cudaGetSymbolAddress((void**)&a_ptr, g_a);

    k_init<<<(NN + 255) / 256, 256>>>();
    k_count4<<<(EE / 4 + 255) / 256, 256>>>((const int4*)col);
    k_scanA<<<(NN + 1023) / 1024, 1024>>>();
    k_scanB<<<(NN + 1023) / 1024, 1024>>>();
    k_scatter4<<<(EE / 4 + 255) / 256, 256>>>((const int4*)row, (const int4*)col);

    k_gemm_tc<<<(NN + 127) / 128, 256>>>(x, W1, h_ptr);
    k_agg<false><<<(NN + 7) / 8, 256>>>(h_ptr, b1, a_ptr);
    k_gemm_tc<<<(NN + 127) / 128, 256>>>(a_ptr, W2, h_ptr);
    k_agg<true><<<(NN + 7) / 8, 256>>>(h_ptr, b2, nullptr);
    k_cls<<<1, 64>>>(Wc, bc, (float*)d_out);
}

// round 3
// speedup vs baseline: 1.6618x; 1.6618x over previous
#include <cuda_runtime.h>

#define NN 50000
#define EE 800000
#define D  128

// ---------------- persistent device scratch --------------------------------
__device__ int   g_degE[NN];
__device__ float g_dinv[NN];
__device__ int   g_rowPtr[NN + 1];
__device__ int   g_cursor[NN];
__device__ int   g_blkSum[64];
__device__ int   g_src[EE];
__device__ float g_h[(size_t)NN * D];
__device__ float g_a[(size_t)NN * D];
__device__ float g_gsum[D];
__device__ uint4 g_Wf1[8192];   // W1 fragments: hi/lo, mma order (128KB)
__device__ uint4 g_Wf2[8192];   // W2 fragments

// ---------------- setup -----------------------------------------------------
__global__ void k_init() {
    int i = blockIdx.x * blockDim.x + threadIdx.x;
    if (i < NN) { g_degE[i] = 0; g_cursor[i] = 0; }
    if (i < D) g_gsum[i] = 0.f;
    if (i == 0) g_rowPtr[NN] = EE;
}

__global__ void k_count4(const int4* __restrict__ col4) {
    int idx = blockIdx.x * blockDim.x + threadIdx.x;
    if (idx < EE / 4) {
        int4 c = __ldg(&col4[idx]);
        atomicAdd(&g_degE[c.x], 1);
        atomicAdd(&g_degE[c.y], 1);
        atomicAdd(&g_degE[c.z], 1);
        atomicAdd(&g_degE[c.w], 1);
    }
}

__global__ void k_scanA() {
    __shared__ int sW[32];
    int t = threadIdx.x, b = blockIdx.x;
    int i = b * 1024 + t;
    int v = (i < NN) ? g_degE[i] : 0;
    if (i < NN) g_dinv[i] = rsqrtf((float)(v + 1));   // +1 self loop
    int lane = t & 31, wid = t >> 5;
    int incl = v;
#pragma unroll
    for (int d = 1; d < 32; d <<= 1) {
        int n = __shfl_up_sync(0xffffffffu, incl, d);
        if (lane >= d) incl += n;
    }
    if (lane == 31) sW[wid] = incl;
    __syncthreads();
    if (wid == 0) {
        int wv = sW[lane];
#pragma unroll
        for (int d = 1; d < 32; d <<= 1) {
            int n = __shfl_up_sync(0xffffffffu, wv, d);
            if (lane >= d) wv += n;
        }
        sW[lane] = wv;
    }
    __syncthreads();
    int woff = (wid > 0) ? sW[wid - 1] : 0;
    if (i < NN) g_rowPtr[i] = woff + incl - v;
    if (t == 1023) g_blkSum[b] = woff + incl;
}

__global__ void k_scanB() {
    __shared__ int sArr[64];
    __shared__ int sOff;
    int t = threadIdx.x, b = blockIdx.x;
    if (t < 49) sArr[t] = g_blkSum[t];
    __syncthreads();
    if (t == 0) { int s = 0; for (int j = 0; j < b; j++) s += sArr[j]; sOff = s; }
    __syncthreads();
    int i = b * 1024 + t;
    if (i < NN) g_rowPtr[i] += sOff;
}

__global__ void k_scatter4(const int4* __restrict__ row4, const int4* __restrict__ col4) {
    int idx = blockIdx.x * blockDim.x + threadIdx.x;
    if (idx < EE / 4) {
        int4 r = __ldg(&row4[idx]);
        int4 c = __ldg(&col4[idx]);
        g_src[__ldg(&g_rowPtr[c.x]) + atomicAdd(&g_cursor[c.x], 1)] = r.x;
        g_src[__ldg(&g_rowPtr[c.y]) + atomicAdd(&g_cursor[c.y], 1)] = r.y;
        g_src[__ldg(&g_rowPtr[c.z]) + atomicAdd(&g_cursor[c.z], 1)] = r.z;
        g_src[__ldg(&g_rowPtr[c.w]) + atomicAdd(&g_cursor[c.w], 1)] = r.w;
    }
}

// ---------------- tf32 helpers ----------------------------------------------
__device__ __forceinline__ void split_tf32(float x, unsigned& hi, unsigned& lo) {
    asm("cvt.rna.tf32.f32 %0, %1;" : "=r"(hi) : "f"(x));
    float r = x - __uint_as_float(hi);
    asm("cvt.rna.tf32.f32 %0, %1;" : "=r"(lo) : "f"(r));
}

__device__ __forceinline__ void mma_tf32(float* d, const unsigned* a, unsigned b0, unsigned b1) {
    asm volatile(
        "mma.sync.aligned.m16n8k8.row.col.f32.tf32.tf32.f32 "
        "{%0,%1,%2,%3},{%4,%5,%6,%7},{%8,%9},{%0,%1,%2,%3};\n"
        : "+f"(d[0]), "+f"(d[1]), "+f"(d[2]), "+f"(d[3])
        : "r"(a[0]), "r"(a[1]), "r"(a[2]), "r"(a[3]), "r"(b0), "r"(b1));
}

// W -> fragment-ordered hi/lo splits.
// index i = ((kc*2+ks)*16 + ntg)*32 + lane ; value = {b0h, b1h, b0l, b1l}
// b0: k = kc*16+ks*8+(lane&3),   n = ntg*8 + (lane>>2)
// b1: k += 4
__global__ void k_prepW(const float* __restrict__ W, uint4* __restrict__ out) {
    int i = blockIdx.x * 256 + threadIdx.x;     // 0..8191
    int lane = i & 31;
    int ntg = (i >> 5) & 15;
    int kss = i >> 9;                            // kc*2+ks : 0..15
    int k = kss * 8 + (lane & 3);
    int n = ntg * 8 + (lane >> 2);
    float w0 = __ldg(&W[k * 128 + n]);
    float w1 = __ldg(&W[(k + 4) * 128 + n]);
    unsigned h0, l0, h1, l1;
    split_tf32(w0, h0, l0);
    split_tf32(w1, h1, l1);
    out[i] = make_uint4(h0, h1, l0, l1);
}

// ---------------- tensor-core GEMM (3xTF32): Y = X @ W ----------------------
// Block 256 thr / 8 warps, tile M=128 N=128 K=128 (full-K, staged once).
// X raw in padded smem; A fragments via conflict-free scalar LDS + reg split.
// B fragments streamed from precomputed global fragment array (LDG.128).
#define SXLD 132   // padded row stride (floats)

__global__ void __launch_bounds__(256) k_gemm_tc(const float* __restrict__ X,
                                                 const uint4* __restrict__ Wf,
                                                 float* __restrict__ Y) {
    extern __shared__ float sX[];   // 128 * 132 floats = 67584 B

    const int t = threadIdx.x;
    const int lane = t & 31;
    const int w = t >> 5;
    const int wm = w >> 2;          // 0..1
    const int wn = w & 3;           // 0..3
    const int blkRow = blockIdx.x * 128;

    // ---- stage full X tile (one sync) ----
#pragma unroll
    for (int i = 0; i < 16; i++) {
        int idx = t + i * 256;           // 0..4095 float4 slots
        int row = idx >> 5;
        int col = (idx & 31) * 4;
        int gr = blkRow + row;
        float4 v = (gr < NN) ? *(const float4*)(X + (size_t)gr * 128 + col)
                             : make_float4(0.f, 0.f, 0.f, 0.f);
        *(float4*)(sX + row * SXLD + col) = v;
    }
    __syncthreads();

    float acc[4][4][4];
#pragma unroll
    for (int i = 0; i < 4; i++)
#pragma unroll
        for (int j = 0; j < 4; j++)
#pragma unroll
            for (int k = 0; k < 4; k++) acc[i][j][k] = 0.f;

    const int r0 = lane >> 2;       // 0..7
    const int c0 = lane & 3;        // 0..3

#pragma unroll
    for (int kss = 0; kss < 16; kss++) {       // kc*2+ks
        const int kb = kss * 8;
        // B fragments for this warp's 4 n-tiles
        const uint4* bf = Wf + ((size_t)kss * 16 + wn * 4) * 32 + lane;
        uint4 bb[4];
#pragma unroll
        for (int nt = 0; nt < 4; nt++) bb[nt] = __ldg(&bf[nt * 32]);

#pragma unroll
        for (int mt = 0; mt < 4; mt++) {
            const int rb = wm * 64 + mt * 16;
            const float* base = sX + (rb + r0) * SXLD + kb + c0;
            float a0 = base[0];
            float a1 = base[8 * SXLD];
            float a2 = base[4];
            float a3 = base[8 * SXLD + 4];
            unsigned ah[4], al[4];
            split_tf32(a0, ah[0], al[0]);
            split_tf32(a1, ah[1], al[1]);
            split_tf32(a2, ah[2], al[2]);
            split_tf32(a3, ah[3], al[3]);
#pragma unroll
            for (int nt = 0; nt < 4; nt++) {
                mma_tf32(acc[mt][nt], al, bb[nt].x, bb[nt].y);   // Al*Bh
                mma_tf32(acc[mt][nt], ah, bb[nt].z, bb[nt].w);   // Ah*Bl
                mma_tf32(acc[mt][nt], ah, bb[nt].x, bb[nt].y);   // Ah*Bh
            }
        }
    }

    // ---- epilogue ----
#pragma unroll
    for (int mt = 0; mt < 4; mt++) {
#pragma unroll
        for (int nt = 0; nt < 4; nt++) {
            int row = blkRow + wm * 64 + mt * 16 + (lane >> 2);
            int col = wn * 32 + nt * 8 + (lane & 3) * 2;
            if (row < NN)
                *(float2*)(Y + (size_t)row * 128 + col) =
                    make_float2(acc[mt][nt][0], acc[mt][nt][1]);
            if (row + 8 < NN)
                *(float2*)(Y + (size_t)(row + 8) * 128 + col) =
                    make_float2(acc[mt][nt][2], acc[mt][nt][3]);
        }
    }
}

// ---------------- sparse aggregation (warp per node) -------------------------
template <bool POOL>
__global__ void __launch_bounds__(256) k_agg(const float* __restrict__ H,
                                             const float* __restrict__ bias,
                                             float* __restrict__ O) {
    __shared__ float sPool[128];
    const int lane = threadIdx.x & 31;
    const int w = threadIdx.x >> 5;
    if (POOL) {
        if (threadIdx.x < 128) sPool[threadIdx.x] = 0.f;
        __syncthreads();
    }
    const int node = blockIdx.x * 8 + w;
    if (node < NN) {
        const int s = g_rowPtr[node];
        const int e = g_rowPtr[node + 1];
        const float4* Hv = (const float4*)H;
        float4 acc0 = make_float4(0.f, 0.f, 0.f, 0.f);
        float4 acc1 = make_float4(0.f, 0.f, 0.f, 0.f);
        int i = s;
        for (; i + 1 < e; i += 2) {
            int r0 = __ldg(&g_src[i]);
            int r1 = __ldg(&g_src[i + 1]);
            float d0 = g_dinv[r0], d1 = g_dinv[r1];
            float4 v0 = Hv[(size_t)r0 * 32 + lane];
            float4 v1 = Hv[(size_t)r1 * 32 + lane];
            acc0.x += d0 * v0.x; acc0.y += d0 * v0.y;
            acc0.z += d0 * v0.z; acc0.w += d0 * v0.w;
            acc1.x += d1 * v1.x; acc1.y += d1 * v1.y;
            acc1.z += d1 * v1.z; acc1.w += d1 * v1.w;
        }
        if (i < e) {
            int r0 = __ldg(&g_src[i]);
            float d0 = g_dinv[r0];
            float4 v0 = Hv[(size_t)r0 * 32 + lane];
            acc0.x += d0 * v0.x; acc0.y += d0 * v0.y;
            acc0.z += d0 * v0.z; acc0.w += d0 * v0.w;
        }
        acc0.x += acc1.x; acc0.y += acc1.y; acc0.z += acc1.z; acc0.w += acc1.w;
        const float dc = g_dinv[node];
        const float dc2 = dc * dc;
        float4 sv = Hv[(size_t)node * 32 + lane];
        float4 b = ((const float4*)bias)[lane];
        float4 res;
        res.x = fmaxf(dc * acc0.x + dc2 * sv.x + b.x, 0.f);
        res.y = fmaxf(dc * acc0.y + dc2 * sv.y + b.y, 0.f);
        res.z = fmaxf(dc * acc0.z + dc2 * sv.z + b.z, 0.f);
        res.w = fmaxf(dc * acc0.w + dc2 * sv.w + b.w, 0.f);
        if (!POOL) {
            *(float4*)(O + (size_t)node * 128 + lane * 4) = res;
        } else {
            atomicAdd(&sPool[lane * 4 + 0], res.x);
            atomicAdd(&sPool[lane * 4 + 1], res.y);
            atomicAdd(&sPool[lane * 4 + 2], res.z);
            atomicAdd(&sPool[lane * 4 + 3], res.w);
        }
    }
    if (POOL) {
        __syncthreads();
        if (threadIdx.x < 128) atomicAdd(&g_gsum[threadIdx.x], sPool[threadIdx.x]);
    }
}

// ---------------- classifier head --------------------------------------------
__global__ void k_cls(const float* __restrict__ Wc, const float* __restrict__ bc,
                      float* __restrict__ out) {
    int o = threadIdx.x;
    if (o < 40) {
        float acc = 0.f;
        for (int k = 0; k < 128; k++) acc += g_gsum[k] * Wc[k * 40 + o];
        out[o] = acc * (1.0f / (float)NN) + bc[o];
    }
}

// ---------------- launch ------------------------------------------------------
extern "C" void kernel_launch(void* const* d_in, const int* in_sizes, int n_in,
                              void* d_out, int out_size) {
    const float* x  = (const float*)d_in[0];
    const int*   ei = (const int*)d_in[1];
    const float* W1 = (const float*)d_in[2];
    const float* b1 = (const float*)d_in[3];
    const float* W2 = (const float*)d_in[4];
    const float* b2 = (const float*)d_in[5];
    const float* Wc = (const float*)d_in[6];
    const float* bc = (const float*)d_in[7];
    const int* row = ei;
    const int* col = ei + EE;

    float *h_ptr, *a_ptr;
    cudaGetSymbolAddress((void**)&h_ptr, g_h);
    cudaGetSymbolAddress((void**)&a_ptr, g_a);
    uint4 *wf1, *wf2;
    cudaGetSymbolAddress((void**)&wf1, g_Wf1);
    cudaGetSymbolAddress((void**)&wf2, g_Wf2);

    static int smemSet = 0;
    if (!smemSet) {
        cudaFuncSetAttribute(k_gemm_tc, cudaFuncAttributeMaxDynamicSharedMemorySize,
                             128 * SXLD * 4);
        smemSet = 1;
    }

    k_init<<<(NN + 255) / 256, 256>>>();
    k_prepW<<<32, 256>>>(W1, wf1);
    k_prepW<<<32, 256>>>(W2, wf2);
    k_count4<<<(EE / 4 + 255) / 256, 256>>>((const int4*)col);
    k_scanA<<<(NN + 1023) / 1024, 1024>>>();
    k_scanB<<<(NN + 1023) / 1024, 1024>>>();
    k_scatter4<<<(EE / 4 + 255) / 256, 256>>>((const int4*)row, (const int4*)col);

    k_gemm_tc<<<(NN + 127) / 128, 256, 128 * SXLD * 4>>>(x, wf1, h_ptr);
    k_agg<false><<<(NN + 7) / 8, 256>>>(h_ptr, b1, a_ptr);
    k_gemm_tc<<<(NN + 127) / 128, 256, 128 * SXLD * 4>>>(a_ptr, wf2, h_ptr);
    k_agg<true><<<(NN + 7) / 8, 256>>>(h_ptr, b2, nullptr);
    k_cls<<<1, 64>>>(Wc, bc, (float*)d_out);
}

// round 4
// speedup vs baseline: 2.1444x; 1.2904x over previous
#include <cuda_runtime.h>
#include <cuda_fp16.h>

#define NN 50000
#define EE 800000
#define D  128

// ---------------- persistent device scratch --------------------------------
__device__ int    g_degE[NN];
__device__ float  g_dinv[NN];
__device__ int    g_rowPtr[NN + 1];
__device__ int    g_cursor[NN];
__device__ int    g_blkSum[64];
__device__ int    g_src[EE];
__device__ __half g_hh[(size_t)NN * D];   // GEMM output, fp16
__device__ float  g_a[(size_t)NN * D];    // post-aggregation features, fp32
__device__ float  g_gsum[D];
__device__ uint4  g_Wf1[4096];            // W1 fp16 hi/lo fragments (64KB)
__device__ uint4  g_Wf2[4096];

// ---------------- setup -----------------------------------------------------
__global__ void k_init() {
    int i = blockIdx.x * blockDim.x + threadIdx.x;
    if (i < NN) { g_degE[i] = 0; g_cursor[i] = 0; }
    if (i < D) g_gsum[i] = 0.f;
    if (i == 0) g_rowPtr[NN] = EE;
}

__global__ void k_count4(const int4* __restrict__ col4) {
    int idx = blockIdx.x * blockDim.x + threadIdx.x;
    if (idx < EE / 4) {
        int4 c = __ldg(&col4[idx]);
        atomicAdd(&g_degE[c.x], 1);
        atomicAdd(&g_degE[c.y], 1);
        atomicAdd(&g_degE[c.z], 1);
        atomicAdd(&g_degE[c.w], 1);
    }
}

__global__ void k_scanA() {
    __shared__ int sW[32];
    int t = threadIdx.x, b = blockIdx.x;
    int i = b * 1024 + t;
    int v = (i < NN) ? g_degE[i] : 0;
    if (i < NN) g_dinv[i] = rsqrtf((float)(v + 1));   // +1 self loop
    int lane = t & 31, wid = t >> 5;
    int incl = v;
#pragma unroll
    for (int d = 1; d < 32; d <<= 1) {
        int n = __shfl_up_sync(0xffffffffu, incl, d);
        if (lane >= d) incl += n;
    }
    if (lane == 31) sW[wid] = incl;
    __syncthreads();
    if (wid == 0) {
        int wv = sW[lane];
#pragma unroll
        for (int d = 1; d < 32; d <<= 1) {
            int n = __shfl_up_sync(0xffffffffu, wv, d);
            if (lane >= d) wv += n;
        }
        sW[lane] = wv;
    }
    __syncthreads();
    int woff = (wid > 0) ? sW[wid - 1] : 0;
    if (i < NN) g_rowPtr[i] = woff + incl - v;
    if (t == 1023) g_blkSum[b] = woff + incl;
}

__global__ void k_scanB() {
    __shared__ int sArr[64];
    __shared__ int sOff;
    int t = threadIdx.x, b = blockIdx.x;
    if (t < 49) sArr[t] = g_blkSum[t];
    __syncthreads();
    if (t == 0) { int s = 0; for (int j = 0; j < b; j++) s += sArr[j]; sOff = s; }
    __syncthreads();
    int i = b * 1024 + t;
    if (i < NN) g_rowPtr[i] += sOff;
}

__global__ void k_scatter4(const int4* __restrict__ row4, const int4* __restrict__ col4) {
    int idx = blockIdx.x * blockDim.x + threadIdx.x;
    if (idx < EE / 4) {
        int4 r = __ldg(&row4[idx]);
        int4 c = __ldg(&col4[idx]);
        g_src[__ldg(&g_rowPtr[c.x]) + atomicAdd(&g_cursor[c.x], 1)] = r.x;
        g_src[__ldg(&g_rowPtr[c.y]) + atomicAdd(&g_cursor[c.y], 1)] = r.y;
        g_src[__ldg(&g_rowPtr[c.z]) + atomicAdd(&g_cursor[c.z], 1)] = r.z;
        g_src[__ldg(&g_rowPtr[c.w]) + atomicAdd(&g_cursor[c.w], 1)] = r.w;
    }
}

// ---------------- fp16 split helpers -----------------------------------------
__device__ __forceinline__ void split_f16(float x, __half& hi, __half& lo) {
    hi = __float2half_rn(x);
    lo = __float2half_rn(x - __half2float(hi));
}

// pack one fp32 as {hi(fp16) in low 16, lo(fp16) in high 16}
__device__ __forceinline__ unsigned packsplit(float x) {
    __half hi, lo;
    split_f16(x, hi, lo);
    __half2 p = __halves2half2(hi, lo);
    return *(unsigned*)&p;
}

__device__ __forceinline__ void mma_f16(float* d, unsigned a0, unsigned a1,
                                        unsigned a2, unsigned a3,
                                        unsigned b0, unsigned b1) {
    asm volatile(
        "mma.sync.aligned.m16n8k16.row.col.f32.f16.f16.f32 "
        "{%0,%1,%2,%3},{%4,%5,%6,%7},{%8,%9},{%0,%1,%2,%3};\n"
        : "+f"(d[0]), "+f"(d[1]), "+f"(d[2]), "+f"(d[3])
        : "r"(a0), "r"(a1), "r"(a2), "r"(a3), "r"(b0), "r"(b1));
}

// W -> fp16 hi/lo fragments in m16n8k16 B order.
// i = (kc*16 + ntg)*32 + lane; kc 0..7, ntg 0..15
// b0 pair: k = kc*16+(lane&3)*2 (+1),  n = ntg*8+(lane>>2);  b1: k+8
__global__ void k_prepW(const float* __restrict__ W, uint4* __restrict__ out) {
    int i = blockIdx.x * 256 + threadIdx.x;      // 0..4095
    int lane = i & 31;
    int ntg = (i >> 5) & 15;
    int kc = i >> 9;
    int n = ntg * 8 + (lane >> 2);
    int k0 = kc * 16 + (lane & 3) * 2;
    float w00 = __ldg(&W[k0 * 128 + n]);
    float w01 = __ldg(&W[(k0 + 1) * 128 + n]);
    float w10 = __ldg(&W[(k0 + 8) * 128 + n]);
    float w11 = __ldg(&W[(k0 + 9) * 128 + n]);
    __half h00, l00, h01, l01, h10, l10, h11, l11;
    split_f16(w00, h00, l00);
    split_f16(w01, h01, l01);
    split_f16(w10, h10, l10);
    split_f16(w11, h11, l11);
    __half2 bh0 = __halves2half2(h00, h01);
    __half2 bh1 = __halves2half2(h10, h11);
    __half2 bl0 = __halves2half2(l00, l01);
    __half2 bl1 = __halves2half2(l10, l11);
    out[i] = make_uint4(*(unsigned*)&bh0, *(unsigned*)&bh1,
                        *(unsigned*)&bl0, *(unsigned*)&bl1);
}

// ---------------- tensor-core GEMM (3xFP16): Hh = X @ W ---------------------
// Block 256 thr / 8 warps, tile M=128 N=128 K=128. X staged once as packed
// {hi,lo} words; A fragments = 4 LDS.64 + 8 PRMT. B fragments from global.
#define SXP 132   // padded row stride (uint words)

__global__ void __launch_bounds__(256) k_gemm_tc(const float* __restrict__ X,
                                                 const uint4* __restrict__ Wf,
                                                 __half* __restrict__ Y) {
    extern __shared__ unsigned sXu[];   // 128 * 132 words = 67584 B

    const int t = threadIdx.x;
    const int lane = t & 31;
    const int w = t >> 5;
    const int wm = w >> 2;          // 0..1
    const int wn = w & 3;           // 0..3
    const int blkRow = blockIdx.x * 128;

    // ---- stage + split X tile (one sync) ----
#pragma unroll
    for (int i = 0; i < 16; i++) {
        int idx = t + i * 256;
        int row = idx >> 5;
        int col = (idx & 31) * 4;
        int gr = blkRow + row;
        float4 v = (gr < NN) ? *(const float4*)(X + (size_t)gr * 128 + col)
                             : make_float4(0.f, 0.f, 0.f, 0.f);
        uint4 pv = make_uint4(packsplit(v.x), packsplit(v.y),
                              packsplit(v.z), packsplit(v.w));
        *(uint4*)(sXu + row * SXP + col) = pv;
    }
    __syncthreads();

    float acc[4][4][4];
#pragma unroll
    for (int i = 0; i < 4; i++)
#pragma unroll
        for (int j = 0; j < 4; j++)
#pragma unroll
            for (int k = 0; k < 4; k++) acc[i][j][k] = 0.f;

    const int r0 = lane >> 2;
    const int c0 = (lane & 3) * 2;

#pragma unroll
    for (int kc = 0; kc < 8; kc++) {
        const uint4* bf = Wf + ((size_t)kc * 16 + wn * 4) * 32 + lane;
        uint4 bb[4];
#pragma unroll
        for (int nt = 0; nt < 4; nt++) bb[nt] = __ldg(&bf[nt * 32]);

#pragma unroll
        for (int mt = 0; mt < 4; mt++) {
            const int rb = wm * 64 + mt * 16;
            const unsigned* base = sXu + (rb + r0) * SXP + kc * 16 + c0;
            uint2 p0 = *(const uint2*)(base);               // row r,   k,k+1
            uint2 p1 = *(const uint2*)(base + 8 * SXP);     // row r+8
            uint2 q0 = *(const uint2*)(base + 8);           // row r,   k+8,k+9
            uint2 q1 = *(const uint2*)(base + 8 * SXP + 8); // row r+8
            unsigned ah0 = __byte_perm(p0.x, p0.y, 0x5410);
            unsigned al0 = __byte_perm(p0.x, p0.y, 0x7632);
            unsigned ah1 = __byte_perm(p1.x, p1.y, 0x5410);
            unsigned al1 = __byte_perm(p1.x, p1.y, 0x7632);
            unsigned ah2 = __byte_perm(q0.x, q0.y, 0x5410);
            unsigned al2 = __byte_perm(q0.x, q0.y, 0x7632);
            unsigned ah3 = __byte_perm(q1.x, q1.y, 0x5410);
            unsigned al3 = __byte_perm(q1.x, q1.y, 0x7632);
#pragma unroll
            for (int nt = 0; nt < 4; nt++) {
                mma_f16(acc[mt][nt], al0, al1, al2, al3, bb[nt].x, bb[nt].y); // Al*Bh
                mma_f16(acc[mt][nt], ah0, ah1, ah2, ah3, bb[nt].z, bb[nt].w); // Ah*Bl
                mma_f16(acc[mt][nt], ah0, ah1, ah2, ah3, bb[nt].x, bb[nt].y); // Ah*Bh
            }
        }
    }

    // ---- epilogue: store fp16 ----
#pragma unroll
    for (int mt = 0; mt < 4; mt++) {
#pragma unroll
        for (int nt = 0; nt < 4; nt++) {
            int row = blkRow + wm * 64 + mt * 16 + (lane >> 2);
            int col = wn * 32 + nt * 8 + (lane & 3) * 2;
            if (row < NN) {
                __half2 v = __floats2half2_rn(acc[mt][nt][0], acc[mt][nt][1]);
                *(__half2*)(Y + (size_t)row * 128 + col) = v;
            }
            if (row + 8 < NN) {
                __half2 v = __floats2half2_rn(acc[mt][nt][2], acc[mt][nt][3]);
                *(__half2*)(Y + (size_t)(row + 8) * 128 + col) = v;
            }
        }
    }
}

// ---------------- sparse aggregation (warp per node, fp16 gather) -----------
template <bool POOL>
__global__ void __launch_bounds__(256) k_agg(const __half* __restrict__ H,
                                             const float* __restrict__ bias,
                                             float* __restrict__ O) {
    __shared__ float sPool[128];
    const int lane = threadIdx.x & 31;
    const int w = threadIdx.x >> 5;
    if (POOL) {
        if (threadIdx.x < 128) sPool[threadIdx.x] = 0.f;
        __syncthreads();
    }
    const int node = blockIdx.x * 8 + w;
    if (node < NN) {
        const int s = g_rowPtr[node];
        const int e = g_rowPtr[node + 1];
        const uint2* Hv = (const uint2*)H;   // 32 x uint2 (4 halves) per row
        float4 acc0 = make_float4(0.f, 0.f, 0.f, 0.f);
        float4 acc1 = make_float4(0.f, 0.f, 0.f, 0.f);
        int i = s;
        for (; i + 1 < e; i += 2) {
            int r0 = __ldg(&g_src[i]);
            int r1 = __ldg(&g_src[i + 1]);
            float d0 = g_dinv[r0], d1 = g_dinv[r1];
            uint2 u0 = __ldg(&Hv[(size_t)r0 * 32 + lane]);
            uint2 u1 = __ldg(&Hv[(size_t)r1 * 32 + lane]);
            float2 a = __half22float2(*(__half2*)&u0.x);
            float2 b = __half22float2(*(__half2*)&u0.y);
            float2 c = __half22float2(*(__half2*)&u1.x);
            float2 d = __half22float2(*(__half2*)&u1.y);
            acc0.x += d0 * a.x; acc0.y += d0 * a.y;
            acc0.z += d0 * b.x; acc0.w += d0 * b.y;
            acc1.x += d1 * c.x; acc1.y += d1 * c.y;
            acc1.z += d1 * d.x; acc1.w += d1 * d.y;
        }
        if (i < e) {
            int r0 = __ldg(&g_src[i]);
            float d0 = g_dinv[r0];
            uint2 u0 = __ldg(&Hv[(size_t)r0 * 32 + lane]);
            float2 a = __half22float2(*(__half2*)&u0.x);
            float2 b = __half22float2(*(__half2*)&u0.y);
            acc0.x += d0 * a.x; acc0.y += d0 * a.y;
            acc0.z += d0 * b.x; acc0.w += d0 * b.y;
        }
        acc0.x += acc1.x; acc0.y += acc1.y; acc0.z += acc1.z; acc0.w += acc1.w;
        const float dc = g_dinv[node];
        const float dc2 = dc * dc;
        uint2 us = __ldg(&Hv[(size_t)node * 32 + lane]);
        float2 sa = __half22float2(*(__half2*)&us.x);
        float2 sb = __half22float2(*(__half2*)&us.y);
        float4 b4 = ((const float4*)bias)[lane];
        float4 res;
        res.x = fmaxf(dc * acc0.x + dc2 * sa.x + b4.x, 0.f);
        res.y = fmaxf(dc * acc0.y + dc2 * sa.y + b4.y, 0.f);
        res.z = fmaxf(dc * acc0.z + dc2 * sb.x + b4.z, 0.f);
        res.w = fmaxf(dc * acc0.w + dc2 * sb.y + b4.w, 0.f);
        if (!POOL) {
            *(float4*)(O + (size_t)node * 128 + lane * 4) = res;
        } else {
            atomicAdd(&sPool[lane * 4 + 0], res.x);
            atomicAdd(&sPool[lane * 4 + 1], res.y);
            atomicAdd(&sPool[lane * 4 + 2], res.z);
            atomicAdd(&sPool[lane * 4 + 3], res.w);
        }
    }
    if (POOL) {
        __syncthreads();
        if (threadIdx.x < 128) atomicAdd(&g_gsum[threadIdx.x], sPool[threadIdx.x]);
    }
}

// ---------------- classifier head --------------------------------------------
__global__ void k_cls(const float* __restrict__ Wc, const float* __restrict__ bc,
                      float* __restrict__ out) {
    int o = threadIdx.x;
    if (o < 40) {
        float acc = 0.f;
        for (int k = 0; k < 128; k++) acc += g_gsum[k] * Wc[k * 40 + o];
        out[o] = acc * (1.0f / (float)NN) + bc[o];
    }
}

// ---------------- launch ------------------------------------------------------
extern "C" void kernel_launch(void* const* d_in, const int* in_sizes, int n_in,
                              void* d_out, int out_size) {
    const float* x  = (const float*)d_in[0];
    const int*   ei = (const int*)d_in[1];
    const float* W1 = (const float*)d_in[2];
    const float* b1 = (const float*)d_in[3];
    const float* W2 = (const float*)d_in[4];
    const float* b2 = (const float*)d_in[5];
    const float* Wc = (const float*)d_in[6];
    const float* bc = (const float*)d_in[7];
    const int* row = ei;
    const int* col = ei + EE;

    __half* hh_ptr;
    float* a_ptr;
    cudaGetSymbolAddress((void**)&hh_ptr, g_hh);
    cudaGetSymbolAddress((void**)&a_ptr, g_a);
    uint4 *wf1, *wf2;
    cudaGetSymbolAddress((void**)&wf1, g_Wf1);
    cudaGetSymbolAddress((void**)&wf2, g_Wf2);

    static int smemSet = 0;
    if (!smemSet) {
        cudaFuncSetAttribute(k_gemm_tc, cudaFuncAttributeMaxDynamicSharedMemorySize,
                             128 * SXP * 4);
        smemSet = 1;
    }

    k_init<<<(NN + 255) / 256, 256>>>();
    k_prepW<<<16, 256>>>(W1, wf1);
    k_prepW<<<16, 256>>>(W2, wf2);
    k_count4<<<(EE / 4 + 255) / 256, 256>>>((const int4*)col);
    k_scanA<<<(NN + 1023) / 1024, 1024>>>();
    k_scanB<<<(NN + 1023) / 1024, 1024>>>();
    k_scatter4<<<(EE / 4 + 255) / 256, 256>>>((const int4*)row, (const int4*)col);

    k_gemm_tc<<<(NN + 127) / 128, 256, 128 * SXP * 4>>>(x, wf1, hh_ptr);
    k_agg<false><<<(NN + 7) / 8, 256>>>(hh_ptr, b1, a_ptr);
    k_gemm_tc<<<(NN + 127) / 128, 256, 128 * SXP * 4>>>(a_ptr, wf2, hh_ptr);
    k_agg<true><<<(NN + 7) / 8, 256>>>(hh_ptr, b2, nullptr);
    k_cls<<<1, 64>>>(Wc, bc, (float*)d_out);
}